// round 5
// baseline (speedup 1.0000x reference)
#include <cuda_runtime.h>
#include <cuda_fp16.h>
#include <math.h>

#define B   8
#define C1  256
#define HW1 4096
#define C2  512
#define HW2 1024

#define TPB  256
#define STPB 1024

#define CCH  8                  // channels per tile (== warps per block)
#define HWCH 1024               // hw elements per tile (256 thr * float4)
#define NCG1 16                 // channel-group pairs, level1 (32 cc / 2)
#define NH1  (HW1 / HWCH)       // 4
#define NCG2 32                 // level2 (64 cc / 2)
#define NH2  (HW2 / HWCH)       // 1
#define P1B1 (B * NCG1 * NH1)   // 512 blocks, level1
#define P1B2 (B * NCG2 * NH2)   // 256 blocks, level2
#define P1TOT (P1B1 + P1B2)     // 768: one balanced wave, 2 tiles each

#define P2CH 16                 // channels per pass2 block
#define P2B1 (B * (C1 / P2CH) * (HW1 / HWCH))   // 8*16*4 = 512
#define P2B2 (B * (C2 / P2CH) * (HW2 / HWCH))   // 8*32*1 = 256
#define P2TOT (P2B1 + P2B2)                     // 768

// ---------------- scratch (device globals; no runtime allocation) -----------
__device__ __align__(128) float g_Gs1p[2][NCG1][B * HW1];   // |x| channel-sum partials
__device__ __align__(128) float g_Gs2p[2][NCG2][B * HW2];
__device__ __align__(128) float g_Gc1p[2][B * C1][NH1];     // |x| spatial-sum partials
__device__ __align__(128) float g_Gc2p[2][B * C2][NH2];

__device__ __align__(128) __half g_d1[B * C1 * HW1];        // fp16 stash of (s-t)
__device__ __align__(128) __half g_d2[B * C2 * HW2];

__device__ __align__(128) float g_Ms1[B * HW1];
__device__ __align__(128) float g_Mc1[B * C1];
__device__ __align__(128) float g_Ms2[B * HW2];
__device__ __align__(128) float g_Mc2[B * C2];

__device__ double g_latpart[16];
__device__ float  g_p2[P2TOT];
__device__ unsigned g_count = 0;

union F2D { float2 f2; double d; };

// ---------------- reduce helpers --------------------------------------------
__device__ __forceinline__ float blockReduceSum(float v) {
    __shared__ float sh[32];
    int lane = threadIdx.x & 31, warp = threadIdx.x >> 5;
    int nw = blockDim.x >> 5;
#pragma unroll
    for (int o = 16; o > 0; o >>= 1) v += __shfl_down_sync(0xffffffffu, v, o);
    __syncthreads();
    if (lane == 0) sh[warp] = v;
    __syncthreads();
    if (threadIdx.x == 0) {
        float r = 0.f;
        for (int w = 0; w < nw; w++) r += sh[w];
        sh[0] = r;
    }
    __syncthreads();
    return sh[0];
}

__device__ __forceinline__ float blockReduceMax(float v) {
    __shared__ float sh[32];
    int lane = threadIdx.x & 31, warp = threadIdx.x >> 5;
    int nw = blockDim.x >> 5;
#pragma unroll
    for (int o = 16; o > 0; o >>= 1) v = fmaxf(v, __shfl_down_sync(0xffffffffu, v, o));
    __syncthreads();
    if (lane == 0) sh[warp] = v;
    __syncthreads();
    if (threadIdx.x == 0) {
        float r = sh[0];
        for (int w = 1; w < nw; w++) r = fmaxf(r, sh[w]);
        sh[0] = r;
    }
    __syncthreads();
    return sh[0];
}

// ---------------- pass 1: 2 paired tiles per block, register Gs accum --------
template <int Cc, int HWc, int NCG, int NH>
__device__ __forceinline__ void pass1_pair(
    const float* __restrict__ s, const float* __restrict__ t,
    __half* __restrict__ dst,
    float* __restrict__ Gsp_s, float* __restrict__ Gsp_t,   // [NCG][B*HWc]
    float* __restrict__ Gcp_s, float* __restrict__ Gcp_t,   // [B*Cc][NH]
    float2 (*stage)[TPB],
    int blk)
{
    const int tid = threadIdx.x;
    const int lane = tid & 31, warp = tid >> 5;
    const int b  = blk / (NCG * NH);
    const int r  = blk % (NCG * NH);
    const int cg = r / NH;
    const int hh = r % NH;
    const int hwbase = hh * HWCH;
    constexpr int STR4 = HWc / 4;

    float4 as = make_float4(0.f, 0.f, 0.f, 0.f);
    float4 at = make_float4(0.f, 0.f, 0.f, 0.f);

#pragma unroll
    for (int half = 0; half < 2; half++) {
        const int c0 = (cg + half * NCG) * CCH;
        const size_t base4 = (((size_t)b * Cc + c0) * HWc + hwbase) / 4;
        const float4* ps = (const float4*)s + base4 + tid;
        const float4* pt = (const float4*)t + base4 + tid;
        uint2* pd = (uint2*)dst + base4 + tid;

#pragma unroll
        for (int ci = 0; ci < CCH; ci++) {
            float4 vs = __ldcs(&ps[(size_t)ci * STR4]);   // evict-first
            float4 vt = __ldcs(&pt[(size_t)ci * STR4]);

            __half2 h01 = __floats2half2_rn(vs.x - vt.x, vs.y - vt.y);
            __half2 h23 = __floats2half2_rn(vs.z - vt.z, vs.w - vt.w);
            uint2 u;
            u.x = *reinterpret_cast<const unsigned*>(&h01);
            u.y = *reinterpret_cast<const unsigned*>(&h23);
            pd[(size_t)ci * STR4] = u;

            vs.x = fabsf(vs.x); vs.y = fabsf(vs.y); vs.z = fabsf(vs.z); vs.w = fabsf(vs.w);
            vt.x = fabsf(vt.x); vt.y = fabsf(vt.y); vt.z = fabsf(vt.z); vt.w = fabsf(vt.w);
            as.x += vs.x; as.y += vs.y; as.z += vs.z; as.w += vs.w;
            at.x += vt.x; at.y += vt.y; at.z += vt.z; at.w += vt.w;

            stage[ci][tid] = make_float2((vs.x + vs.y) + (vs.z + vs.w),
                                         (vt.x + vt.y) + (vt.z + vt.w));
        }
        __syncthreads();
        // warp w reduces channel c0+w
        float2 acc = make_float2(0.f, 0.f);
#pragma unroll
        for (int k = 0; k < TPB / 32; k++) {
            float2 v = stage[warp][lane + 32 * k];
            acc.x += v.x; acc.y += v.y;
        }
        F2D u2; u2.f2 = acc;
#pragma unroll
        for (int o = 16; o > 0; o >>= 1) {
            F2D v; v.d = __shfl_down_sync(0xffffffffu, u2.d, o);
            u2.f2.x += v.f2.x; u2.f2.y += v.f2.y;
        }
        if (lane == 0) {
            int idx = (b * Cc + c0 + warp) * NH + hh;
            Gcp_s[idx] = u2.f2.x;
            Gcp_t[idx] = u2.f2.y;
        }
        __syncthreads();   // stage reused by second half
    }

    float4* os = (float4*)(Gsp_s + (size_t)cg * (B * HWc) + b * HWc + hwbase) + tid;
    float4* ot = (float4*)(Gsp_t + (size_t)cg * (B * HWc) + b * HWc + hwbase) + tid;
    *os = as;
    *ot = at;
}

__global__ void pass1_kernel(const float* __restrict__ s1, const float* __restrict__ t1,
                             const float* __restrict__ s2, const float* __restrict__ t2) {
    __shared__ float2 stage[CCH][TPB];   // 16 KB
    int bid = blockIdx.x;
    if (bid < P1B1)
        pass1_pair<C1, HW1, NCG1, NH1>(s1, t1, g_d1,
            &g_Gs1p[0][0][0], &g_Gs1p[1][0][0],
            &g_Gc1p[0][0][0], &g_Gc1p[1][0][0], stage, bid);
    else
        pass1_pair<C2, HW2, NCG2, NH2>(s2, t2, g_d2,
            &g_Gs2p[0][0][0], &g_Gs2p[1][0][0],
            &g_Gc2p[0][0][0], &g_Gc2p[1][0][0], stage, bid - P1B1);
}

// ---------------- softmax + lat (16 blocks; partials L2-resident) ------------
template <int Cc, int HWc, int NCG, int NPART>
__device__ __forceinline__ void softmax_level(
    const float* __restrict__ Gsp_s, const float* __restrict__ Gsp_t,
    const float* __restrict__ Gcp_s, const float* __restrict__ Gcp_t,
    float* __restrict__ Ms, float* __restrict__ Mc,
    int b, float* zbuf, double* latout)
{
    const int tid = threadIdx.x;

    // ---- spatial ----
    float latp = 0.f, mx = -INFINITY;
    for (int i = tid; i < HWc; i += STPB) {
        float ss = 0.f, st = 0.f;
#pragma unroll 8
        for (int p = 0; p < NCG; p++) {
            ss += Gsp_s[(size_t)p * (B * HWc) + b * HWc + i];
            st += Gsp_t[(size_t)p * (B * HWc) + b * HWc + i];
        }
        float d = ss - st;
        latp += d * d;
        float z = (ss + st) * (2.0f / (float)Cc);  // /C then /T (T=0.5)
        zbuf[i] = z;
        mx = fmaxf(mx, z);
    }
    float m = blockReduceMax(mx);
    float se = 0.f;
    for (int i = tid; i < HWc; i += STPB) {
        float e = __expf(zbuf[i] - m);
        zbuf[i] = e;
        se += e;
    }
    float S = blockReduceSum(se);
    float sc = (float)HWc / S;
    for (int i = tid; i < HWc; i += STPB) Ms[b * HWc + i] = zbuf[i] * sc;
    float lat_s = blockReduceSum(latp);

    // ---- channel ----
    float latc = 0.f, mxc = -INFINITY;
    for (int i = tid; i < Cc; i += STPB) {
        float cs = 0.f, ct = 0.f;
#pragma unroll
        for (int k = 0; k < NPART; k++) {
            cs += Gcp_s[(size_t)(b * Cc + i) * NPART + k];
            ct += Gcp_t[(size_t)(b * Cc + i) * NPART + k];
        }
        float d = cs - ct;
        latc += d * d;
        float z = (cs + ct) * (2.0f / (float)HWc);
        zbuf[i] = z;
        mxc = fmaxf(mxc, z);
    }
    float m2 = blockReduceMax(mxc);
    float sec = 0.f;
    for (int i = tid; i < Cc; i += STPB) {
        float e = __expf(zbuf[i] - m2);
        zbuf[i] = e;
        sec += e;
    }
    float Sc = blockReduceSum(sec);
    float scc = (float)Cc / Sc;
    for (int i = tid; i < Cc; i += STPB) Mc[b * Cc + i] = zbuf[i] * scc;
    float lat_c = blockReduceSum(latc);

    if (tid == 0)
        *latout = (double)lat_s / ((double)Cc * (double)Cc) +
                  (double)lat_c / ((double)HWc * (double)HWc);
}

__global__ void softmax_kernel() {
    __shared__ float zbuf[HW1];   // 16 KB
    int bid = blockIdx.x;
    if (bid == 0 && threadIdx.x == 0) g_count = 0;   // reset last-block counter
    if (bid < B)
        softmax_level<C1, HW1, NCG1, NH1>(
            &g_Gs1p[0][0][0], &g_Gs1p[1][0][0],
            &g_Gc1p[0][0][0], &g_Gc1p[1][0][0],
            g_Ms1, g_Mc1, bid, zbuf, &g_latpart[bid]);
    else
        softmax_level<C2, HW2, NCG2, NH2>(
            &g_Gs2p[0][0][0], &g_Gs2p[1][0][0],
            &g_Gc2p[0][0][0], &g_Gc2p[1][0][0],
            g_Ms2, g_Mc2, bid - B, zbuf, &g_latpart[bid]);
}

// ---------------- pass 2: Ms in registers, 16-channel loop, fused final ------
__device__ __forceinline__ void discard_l2(const void* p) {
    unsigned long long g;
    asm("cvta.to.global.u64 %0, %1;" : "=l"(g) : "l"(p));
    asm volatile("discard.global.L2 [%0], 128;" :: "l"(g) : "memory");
}

template <int Cc, int HWc>
__device__ __forceinline__ float pass2_block(
    const __half* __restrict__ dsrc,
    const float* __restrict__ Ms, const float* __restrict__ Mc,
    int b, int c0, int hwbase)
{
    const int tid = threadIdx.x;
    // this thread's 4 fixed hw positions: Ms kept in registers
    float4 ms = *(const float4*)(Ms + (size_t)b * HWc + hwbase + tid * 4);

    float acc = 0.f;
#pragma unroll
    for (int ci = 0; ci < P2CH; ci++) {
        const int c = c0 + ci;
        const uint2* p = (const uint2*)dsrc +
                         (((size_t)b * Cc + c) * HWc + hwbase) / 4 + tid;
        uint2 v = *p;
        float2 f0 = __half22float2(*reinterpret_cast<const __half2*>(&v.x));
        float2 f1 = __half22float2(*reinterpret_cast<const __half2*>(&v.y));
        float e = f0.x * f0.x * ms.x + f0.y * f0.y * ms.y
                + f1.x * f1.x * ms.z + f1.y * f1.y * ms.w;
        acc += e * Mc[b * Cc + c];
    }
    return acc;
}

template <int Cc, int HWc>
__device__ __forceinline__ void pass2_discard_block(
    const __half* dsrc, int b, int c0, int hwbase)
{
    // 16 channels * 16 lines (2KB/chunk) = 256 = TPB: one line per thread
    const int ci = threadIdx.x >> 4;
    const int ln = threadIdx.x & 15;
    const __half* p = dsrc + ((size_t)b * Cc + c0 + ci) * HWc + hwbase + ln * 64;
    discard_l2(p);
}

__global__ void pass2_kernel(float* out, int out_size) {
    int bid = blockIdx.x;
    float acc;
    int b, c0, hwbase;
    if (bid < P2B1) {
        b = bid / ((C1 / P2CH) * (HW1 / HWCH));
        int r = bid % ((C1 / P2CH) * (HW1 / HWCH));
        c0 = (r / (HW1 / HWCH)) * P2CH;
        hwbase = (r % (HW1 / HWCH)) * HWCH;
        acc = pass2_block<C1, HW1>(g_d1, g_Ms1, g_Mc1, b, c0, hwbase);
    } else {
        int id = bid - P2B1;
        b = id / (C2 / P2CH);
        c0 = (id % (C2 / P2CH)) * P2CH;
        hwbase = 0;
        acc = pass2_block<C2, HW2>(g_d2, g_Ms2, g_Mc2, b, c0, hwbase);
    }
    float bl = blockReduceSum(acc);   // __syncthreads inside: loads complete

    if (bid < P2B1) pass2_discard_block<C1, HW1>(g_d1, b, c0, hwbase);
    else            pass2_discard_block<C2, HW2>(g_d2, b, c0, hwbase);

    __shared__ bool isLast;
    if (threadIdx.x == 0) {
        g_p2[bid] = bl;
        __threadfence();
        unsigned old = atomicAdd(&g_count, 1u);
        isLast = (old == P2TOT - 1);
    }
    __syncthreads();
    if (!isLast) return;

    // ---- fused final combine (last block) ----
    __threadfence();
    int tid = threadIdx.x;
    double a1 = 0.0, a2 = 0.0;
    for (int i = tid; i < P2B1; i += TPB) a1 += (double)g_p2[i];
    for (int i = P2B1 + tid; i < P2TOT; i += TPB) a2 += (double)g_p2[i];

    __shared__ double sh1[32], sh2[32];
    int lane = tid & 31, warp = tid >> 5;
#pragma unroll
    for (int o = 16; o > 0; o >>= 1) {
        a1 += __shfl_down_sync(0xffffffffu, a1, o);
        a2 += __shfl_down_sync(0xffffffffu, a2, o);
    }
    if (lane == 0) { sh1[warp] = a1; sh2[warp] = a2; }
    __syncthreads();
    if (tid == 0) {
        double s1 = 0.0, s2 = 0.0;
        for (int w = 0; w < TPB / 32; w++) { s1 += sh1[w]; s2 += sh2[w]; }
        double lat = 0.0;
        for (int i = 0; i < 16; i++) lat += g_latpart[i];
        double lam = sqrt(s1) + sqrt(s2);
        double att = (4e-4 * lat + 2e-2 * lam) / (double)B / 2.0;  // ATT=1, /BS, /2
        out[0] = (float)(att * (double)B);
        if (out_size > 1) out[1] = (float)att;
    }
}

// ---------------- launch ------------------------------------------------------
extern "C" void kernel_launch(void* const* d_in, const int* in_sizes, int n_in,
                              void* d_out, int out_size) {
    const float* stu1 = (const float*)d_in[1];
    const float* tea1 = (const float*)d_in[2];
    const float* stu2 = (const float*)d_in[3];
    const float* tea2 = (const float*)d_in[4];
    float* out = (float*)d_out;

    pass1_kernel<<<P1TOT, TPB>>>(stu1, tea1, stu2, tea2);
    softmax_kernel<<<16, STPB>>>();
    pass2_kernel<<<P2TOT, TPB>>>(out, out_size);
}

// round 6
// speedup vs baseline: 1.0027x; 1.0027x over previous
#include <cuda_runtime.h>
#include <cuda_fp16.h>
#include <math.h>

#define B   8
#define C1  256
#define HW1 4096
#define C2  512
#define HW2 1024

#define TPB  256
#define STPB 1024

#define CCH  8                  // channels per tile half (== warps per block)
#define HWCH 1024               // hw elements per tile (256 thr * float4)
#define NCG1 16                 // channel-group pairs, level1
#define NH1  (HW1 / HWCH)       // 4
#define NCG2 32                 // level2
#define NH2  (HW2 / HWCH)       // 1
#define P1B1 (B * NCG1 * NH1)   // 512
#define P1B2 (B * NCG2 * NH2)   // 256
#define P1TOT (P1B1 + P1B2)     // 768

#define P2CH 16
#define P2B1 (B * (C1 / P2CH) * (HW1 / HWCH))   // 512
#define P2B2 (B * (C2 / P2CH) * (HW2 / HWCH))   // 256
#define P2TOT (P2B1 + P2B2)                     // 768

// ---------------- scratch ----------------------------------------------------
__device__ __align__(128) float g_Gs1p[2][NCG1][B * HW1];
__device__ __align__(128) float g_Gs2p[2][NCG2][B * HW2];
__device__ __align__(128) float g_Gc1p[2][B * C1][NH1];
__device__ __align__(128) float g_Gc2p[2][B * C2][NH2];

__device__ __align__(128) __half g_d1[B * C1 * HW1];
__device__ __align__(128) __half g_d2[B * C2 * HW2];

__device__ __align__(128) float g_Ms1[B * HW1];
__device__ __align__(128) float g_Mc1[B * C1];
__device__ __align__(128) float g_Ms2[B * HW2];
__device__ __align__(128) float g_Mc2[B * C2];

__device__ double g_latpart[16];
__device__ float  g_p2[P2TOT];
__device__ unsigned g_count = 0;

union F2D { float2 f2; double d; };

// ---------------- reduce helpers ---------------------------------------------
__device__ __forceinline__ float blockReduceSum(float v) {
    __shared__ float sh[32];
    int lane = threadIdx.x & 31, warp = threadIdx.x >> 5;
    int nw = blockDim.x >> 5;
#pragma unroll
    for (int o = 16; o > 0; o >>= 1) v += __shfl_down_sync(0xffffffffu, v, o);
    __syncthreads();
    if (lane == 0) sh[warp] = v;
    __syncthreads();
    if (threadIdx.x == 0) {
        float r = 0.f;
        for (int w = 0; w < nw; w++) r += sh[w];
        sh[0] = r;
    }
    __syncthreads();
    return sh[0];
}

__device__ __forceinline__ float blockReduceMax(float v) {
    __shared__ float sh[32];
    int lane = threadIdx.x & 31, warp = threadIdx.x >> 5;
    int nw = blockDim.x >> 5;
#pragma unroll
    for (int o = 16; o > 0; o >>= 1) v = fmaxf(v, __shfl_down_sync(0xffffffffu, v, o));
    __syncthreads();
    if (lane == 0) sh[warp] = v;
    __syncthreads();
    if (threadIdx.x == 0) {
        float r = sh[0];
        for (int w = 1; w < nw; w++) r = fmaxf(r, sh[w]);
        sh[0] = r;
    }
    __syncthreads();
    return sh[0];
}

// ---------------- pass 1: 2 halves streamed barrier-free, single sync --------
template <int Cc, int HWc, int NCG, int NH>
__device__ __forceinline__ void pass1_pair(
    const float* __restrict__ s, const float* __restrict__ t,
    __half* __restrict__ dst,
    float* __restrict__ Gsp_s, float* __restrict__ Gsp_t,   // [NCG][B*HWc]
    float* __restrict__ Gcp_s, float* __restrict__ Gcp_t,   // [B*Cc][NH]
    float2 (*stage)[TPB],                                   // [2*CCH][TPB]
    int blk)
{
    const int tid = threadIdx.x;
    const int lane = tid & 31, warp = tid >> 5;
    const int b  = blk / (NCG * NH);
    const int r  = blk % (NCG * NH);
    const int cg = r / NH;
    const int hh = r % NH;
    const int hwbase = hh * HWCH;
    constexpr int STR4 = HWc / 4;

    float4 as = make_float4(0.f, 0.f, 0.f, 0.f);
    float4 at = make_float4(0.f, 0.f, 0.f, 0.f);

    // both halves stream with NO barrier: pure LDG/FADD/STS
#pragma unroll
    for (int half = 0; half < 2; half++) {
        const int c0 = (cg + half * NCG) * CCH;
        const size_t base4 = (((size_t)b * Cc + c0) * HWc + hwbase) / 4;
        const float4* ps = (const float4*)s + base4 + tid;
        const float4* pt = (const float4*)t + base4 + tid;
        uint2* pd = (uint2*)dst + base4 + tid;

#pragma unroll
        for (int ci = 0; ci < CCH; ci++) {
            float4 vs = __ldcs(&ps[(size_t)ci * STR4]);   // evict-first
            float4 vt = __ldcs(&pt[(size_t)ci * STR4]);

            __half2 h01 = __floats2half2_rn(vs.x - vt.x, vs.y - vt.y);
            __half2 h23 = __floats2half2_rn(vs.z - vt.z, vs.w - vt.w);
            uint2 u;
            u.x = *reinterpret_cast<const unsigned*>(&h01);
            u.y = *reinterpret_cast<const unsigned*>(&h23);
            pd[(size_t)ci * STR4] = u;

            vs.x = fabsf(vs.x); vs.y = fabsf(vs.y); vs.z = fabsf(vs.z); vs.w = fabsf(vs.w);
            vt.x = fabsf(vt.x); vt.y = fabsf(vt.y); vt.z = fabsf(vt.z); vt.w = fabsf(vt.w);
            as.x += vs.x; as.y += vs.y; as.z += vs.z; as.w += vs.w;
            at.x += vt.x; at.y += vt.y; at.z += vt.z; at.w += vt.w;

            stage[half * CCH + ci][tid] =
                make_float2((vs.x + vs.y) + (vs.z + vs.w),
                            (vt.x + vt.y) + (vt.z + vt.w));
        }
    }

    // spatial partials: exclusive slots, direct write (pre-sync is fine)
    float4* os = (float4*)(Gsp_s + (size_t)cg * (B * HWc) + b * HWc + hwbase) + tid;
    float4* ot = (float4*)(Gsp_t + (size_t)cg * (B * HWc) + b * HWc + hwbase) + tid;
    *os = as;
    *ot = at;

    __syncthreads();   // the ONLY barrier

    // each warp reduces 2 channels: stage rows {warp, warp+CCH}
#pragma unroll
    for (int half = 0; half < 2; half++) {
        const int row = half * CCH + warp;
        float2 acc = make_float2(0.f, 0.f);
#pragma unroll
        for (int k = 0; k < TPB / 32; k++) {
            float2 v = stage[row][lane + 32 * k];
            acc.x += v.x; acc.y += v.y;
        }
        F2D u2; u2.f2 = acc;
#pragma unroll
        for (int o = 16; o > 0; o >>= 1) {
            F2D v; v.d = __shfl_down_sync(0xffffffffu, u2.d, o);
            u2.f2.x += v.f2.x; u2.f2.y += v.f2.y;
        }
        if (lane == 0) {
            int c = (cg + half * NCG) * CCH + warp;
            int idx = (b * Cc + c) * NH + hh;
            Gcp_s[idx] = u2.f2.x;
            Gcp_t[idx] = u2.f2.y;
        }
    }
}

__global__ void pass1_kernel(const float* __restrict__ s1, const float* __restrict__ t1,
                             const float* __restrict__ s2, const float* __restrict__ t2) {
    __shared__ float2 stage[2 * CCH][TPB];   // 32 KB
    int bid = blockIdx.x;
    if (bid < P1B1)
        pass1_pair<C1, HW1, NCG1, NH1>(s1, t1, g_d1,
            &g_Gs1p[0][0][0], &g_Gs1p[1][0][0],
            &g_Gc1p[0][0][0], &g_Gc1p[1][0][0], stage, bid);
    else
        pass1_pair<C2, HW2, NCG2, NH2>(s2, t2, g_d2,
            &g_Gs2p[0][0][0], &g_Gs2p[1][0][0],
            &g_Gc2p[0][0][0], &g_Gc2p[1][0][0], stage, bid - P1B1);
}

// ---------------- softmax + lat (16 blocks) ----------------------------------
template <int Cc, int HWc, int NCG, int NPART>
__device__ __forceinline__ void softmax_level(
    const float* __restrict__ Gsp_s, const float* __restrict__ Gsp_t,
    const float* __restrict__ Gcp_s, const float* __restrict__ Gcp_t,
    float* __restrict__ Ms, float* __restrict__ Mc,
    int b, float* zbuf, double* latout)
{
    const int tid = threadIdx.x;

    float latp = 0.f, mx = -INFINITY;
    for (int i = tid; i < HWc; i += STPB) {
        float ss = 0.f, st = 0.f;
#pragma unroll 8
        for (int p = 0; p < NCG; p++) {
            ss += Gsp_s[(size_t)p * (B * HWc) + b * HWc + i];
            st += Gsp_t[(size_t)p * (B * HWc) + b * HWc + i];
        }
        float d = ss - st;
        latp += d * d;
        float z = (ss + st) * (2.0f / (float)Cc);
        zbuf[i] = z;
        mx = fmaxf(mx, z);
    }
    float m = blockReduceMax(mx);
    float se = 0.f;
    for (int i = tid; i < HWc; i += STPB) {
        float e = __expf(zbuf[i] - m);
        zbuf[i] = e;
        se += e;
    }
    float S = blockReduceSum(se);
    float sc = (float)HWc / S;
    for (int i = tid; i < HWc; i += STPB) Ms[b * HWc + i] = zbuf[i] * sc;
    float lat_s = blockReduceSum(latp);

    float latc = 0.f, mxc = -INFINITY;
    for (int i = tid; i < Cc; i += STPB) {
        float cs = 0.f, ct = 0.f;
#pragma unroll
        for (int k = 0; k < NPART; k++) {
            cs += Gcp_s[(size_t)(b * Cc + i) * NPART + k];
            ct += Gcp_t[(size_t)(b * Cc + i) * NPART + k];
        }
        float d = cs - ct;
        latc += d * d;
        float z = (cs + ct) * (2.0f / (float)HWc);
        zbuf[i] = z;
        mxc = fmaxf(mxc, z);
    }
    float m2 = blockReduceMax(mxc);
    float sec = 0.f;
    for (int i = tid; i < Cc; i += STPB) {
        float e = __expf(zbuf[i] - m2);
        zbuf[i] = e;
        sec += e;
    }
    float Sc = blockReduceSum(sec);
    float scc = (float)Cc / Sc;
    for (int i = tid; i < Cc; i += STPB) Mc[b * Cc + i] = zbuf[i] * scc;
    float lat_c = blockReduceSum(latc);

    if (tid == 0)
        *latout = (double)lat_s / ((double)Cc * (double)Cc) +
                  (double)lat_c / ((double)HWc * (double)HWc);
}

__global__ void softmax_kernel() {
    __shared__ float zbuf[HW1];
    int bid = blockIdx.x;
    if (bid == 0 && threadIdx.x == 0) g_count = 0;
    if (bid < B)
        softmax_level<C1, HW1, NCG1, NH1>(
            &g_Gs1p[0][0][0], &g_Gs1p[1][0][0],
            &g_Gc1p[0][0][0], &g_Gc1p[1][0][0],
            g_Ms1, g_Mc1, bid, zbuf, &g_latpart[bid]);
    else
        softmax_level<C2, HW2, NCG2, NH2>(
            &g_Gs2p[0][0][0], &g_Gs2p[1][0][0],
            &g_Gc2p[0][0][0], &g_Gc2p[1][0][0],
            g_Ms2, g_Mc2, bid - B, zbuf, &g_latpart[bid]);
}

// ---------------- pass 2: Ms in registers, fused final -----------------------
__device__ __forceinline__ void discard_l2(const void* p) {
    unsigned long long g;
    asm("cvta.to.global.u64 %0, %1;" : "=l"(g) : "l"(p));
    asm volatile("discard.global.L2 [%0], 128;" :: "l"(g) : "memory");
}

template <int Cc, int HWc>
__device__ __forceinline__ float pass2_block(
    const __half* __restrict__ dsrc,
    const float* __restrict__ Ms, const float* __restrict__ Mc,
    int b, int c0, int hwbase)
{
    const int tid = threadIdx.x;
    float4 ms = *(const float4*)(Ms + (size_t)b * HWc + hwbase + tid * 4);

    float acc = 0.f;
#pragma unroll
    for (int ci = 0; ci < P2CH; ci++) {
        const int c = c0 + ci;
        const uint2* p = (const uint2*)dsrc +
                         (((size_t)b * Cc + c) * HWc + hwbase) / 4 + tid;
        uint2 v = *p;
        float2 f0 = __half22float2(*reinterpret_cast<const __half2*>(&v.x));
        float2 f1 = __half22float2(*reinterpret_cast<const __half2*>(&v.y));
        float e = f0.x * f0.x * ms.x + f0.y * f0.y * ms.y
                + f1.x * f1.x * ms.z + f1.y * f1.y * ms.w;
        acc += e * Mc[b * Cc + c];
    }
    return acc;
}

template <int Cc, int HWc>
__device__ __forceinline__ void pass2_discard_block(
    const __half* dsrc, int b, int c0, int hwbase)
{
    const int ci = threadIdx.x >> 4;
    const int ln = threadIdx.x & 15;
    const __half* p = dsrc + ((size_t)b * Cc + c0 + ci) * HWc + hwbase + ln * 64;
    discard_l2(p);
}

__global__ void pass2_kernel(float* out, int out_size) {
    int bid = blockIdx.x;
    float acc;
    int b, c0, hwbase;
    if (bid < P2B1) {
        b = bid / ((C1 / P2CH) * (HW1 / HWCH));
        int r = bid % ((C1 / P2CH) * (HW1 / HWCH));
        c0 = (r / (HW1 / HWCH)) * P2CH;
        hwbase = (r % (HW1 / HWCH)) * HWCH;
        acc = pass2_block<C1, HW1>(g_d1, g_Ms1, g_Mc1, b, c0, hwbase);
    } else {
        int id = bid - P2B1;
        b = id / (C2 / P2CH);
        c0 = (id % (C2 / P2CH)) * P2CH;
        hwbase = 0;
        acc = pass2_block<C2, HW2>(g_d2, g_Ms2, g_Mc2, b, c0, hwbase);
    }
    float bl = blockReduceSum(acc);

    if (bid < P2B1) pass2_discard_block<C1, HW1>(g_d1, b, c0, hwbase);
    else            pass2_discard_block<C2, HW2>(g_d2, b, c0, hwbase);

    __shared__ bool isLast;
    if (threadIdx.x == 0) {
        g_p2[bid] = bl;
        __threadfence();
        unsigned old = atomicAdd(&g_count, 1u);
        isLast = (old == P2TOT - 1);
    }
    __syncthreads();
    if (!isLast) return;

    __threadfence();
    int tid = threadIdx.x;
    double a1 = 0.0, a2 = 0.0;
    for (int i = tid; i < P2B1; i += TPB) a1 += (double)g_p2[i];
    for (int i = P2B1 + tid; i < P2TOT; i += TPB) a2 += (double)g_p2[i];

    __shared__ double sh1[32], sh2[32];
    int lane = tid & 31, warp = tid >> 5;
#pragma unroll
    for (int o = 16; o > 0; o >>= 1) {
        a1 += __shfl_down_sync(0xffffffffu, a1, o);
        a2 += __shfl_down_sync(0xffffffffu, a2, o);
    }
    if (lane == 0) { sh1[warp] = a1; sh2[warp] = a2; }
    __syncthreads();
    if (tid == 0) {
        double s1 = 0.0, s2 = 0.0;
        for (int w = 0; w < TPB / 32; w++) { s1 += sh1[w]; s2 += sh2[w]; }
        double lat = 0.0;
        for (int i = 0; i < 16; i++) lat += g_latpart[i];
        double lam = sqrt(s1) + sqrt(s2);
        double att = (4e-4 * lat + 2e-2 * lam) / (double)B / 2.0;
        out[0] = (float)(att * (double)B);
        if (out_size > 1) out[1] = (float)att;
    }
}

// ---------------- launch ------------------------------------------------------
extern "C" void kernel_launch(void* const* d_in, const int* in_sizes, int n_in,
                              void* d_out, int out_size) {
    const float* stu1 = (const float*)d_in[1];
    const float* tea1 = (const float*)d_in[2];
    const float* stu2 = (const float*)d_in[3];
    const float* tea2 = (const float*)d_in[4];
    float* out = (float*)d_out;

    pass1_kernel<<<P1TOT, TPB>>>(stu1, tea1, stu2, tea2);
    softmax_kernel<<<16, STPB>>>();
    pass2_kernel<<<P2TOT, TPB>>>(out, out_size);
}

// round 7
// speedup vs baseline: 1.1023x; 1.0993x over previous
#include <cuda_runtime.h>
#include <cuda_fp16.h>
#include <math.h>

#define B   8
#define C1  256
#define HW1 4096
#define C2  512
#define HW2 1024

#define TPB  256
#define STPB 1024

#define CCH  8                  // channels per tile (== warps per block)
#define HWCH 1024               // hw elements per tile (256 thr * float4)
#define NC1  (C1 / CCH)         // 32
#define NH1  (HW1 / HWCH)       // 4
#define NC2  (C2 / CCH)         // 64
#define NH2  (HW2 / HWCH)       // 1
#define TILES1 (B * NC1 * NH1)  // 1024
#define TILES2 (B * NC2 * NH2)  // 512

#define P2CH 16
#define P2B1 (B * (C1 / P2CH) * (HW1 / HWCH))   // 512
#define P2B2 (B * (C2 / P2CH) * (HW2 / HWCH))   // 256
#define P2TOT (P2B1 + P2B2)                     // 768

// ---------------- scratch ----------------------------------------------------
__device__ __align__(128) float g_Gs1p[2][NC1][B * HW1];
__device__ __align__(128) float g_Gs2p[2][NC2][B * HW2];
__device__ __align__(128) float g_Gc1p[2][B * C1][NH1];
__device__ __align__(128) float g_Gc2p[2][B * C2][NH2];

__device__ __align__(128) __half g_d1[B * C1 * HW1];
__device__ __align__(128) __half g_d2[B * C2 * HW2];

__device__ __align__(128) float g_Ms1[B * HW1];
__device__ __align__(128) float g_Mc1[B * C1];
__device__ __align__(128) float g_Ms2[B * HW2];
__device__ __align__(128) float g_Mc2[B * C2];

__device__ double g_latpart[16];
__device__ float  g_p2[P2TOT];
__device__ unsigned g_count = 0;

union F2D { float2 f2; double d; };

// ---------------- reduce helpers ---------------------------------------------
__device__ __forceinline__ float blockReduceSum(float v) {
    __shared__ float sh[32];
    int lane = threadIdx.x & 31, warp = threadIdx.x >> 5;
    int nw = blockDim.x >> 5;
#pragma unroll
    for (int o = 16; o > 0; o >>= 1) v += __shfl_down_sync(0xffffffffu, v, o);
    __syncthreads();
    if (lane == 0) sh[warp] = v;
    __syncthreads();
    if (threadIdx.x == 0) {
        float r = 0.f;
        for (int w = 0; w < nw; w++) r += sh[w];
        sh[0] = r;
    }
    __syncthreads();
    return sh[0];
}

__device__ __forceinline__ float blockReduceMax(float v) {
    __shared__ float sh[32];
    int lane = threadIdx.x & 31, warp = threadIdx.x >> 5;
    int nw = blockDim.x >> 5;
#pragma unroll
    for (int o = 16; o > 0; o >>= 1) v = fmaxf(v, __shfl_down_sync(0xffffffffu, v, o));
    __syncthreads();
    if (lane == 0) sh[warp] = v;
    __syncthreads();
    if (threadIdx.x == 0) {
        float r = sh[0];
        for (int w = 1; w < nw; w++) r = fmaxf(r, sh[w]);
        sh[0] = r;
    }
    __syncthreads();
    return sh[0];
}

// ---------------- pass 1: short tiles, high occupancy ------------------------
template <int Cc, int HWc, int NC, int NH>
__device__ __forceinline__ void pass1_tile(
    const float* __restrict__ s, const float* __restrict__ t,
    __half* __restrict__ dst,
    float* __restrict__ Gsp_s, float* __restrict__ Gsp_t,   // [NC][B*HWc]
    float* __restrict__ Gcp_s, float* __restrict__ Gcp_t,   // [B*Cc][NH]
    float2 (*stage)[TPB],
    int tile)
{
    const int tid = threadIdx.x;
    const int lane = tid & 31, warp = tid >> 5;
    const int b  = tile / (NC * NH);
    const int r  = tile % (NC * NH);
    const int cc = r / NH;
    const int hh = r % NH;
    const int hwbase = hh * HWCH;
    const int c0 = cc * CCH;

    const size_t base4 = (((size_t)b * Cc + c0) * HWc + hwbase) / 4;
    const float4* ps = (const float4*)s + base4 + tid;
    const float4* pt = (const float4*)t + base4 + tid;
    uint2* pd = (uint2*)dst + base4 + tid;
    constexpr int STR4 = HWc / 4;

    float4 as = make_float4(0.f, 0.f, 0.f, 0.f);
    float4 at = make_float4(0.f, 0.f, 0.f, 0.f);

    // pure streaming loop: no cross-lane deps, no barriers
#pragma unroll
    for (int ci = 0; ci < CCH; ci++) {
        float4 vs = __ldcs(&ps[(size_t)ci * STR4]);   // evict-first
        float4 vt = __ldcs(&pt[(size_t)ci * STR4]);

        __half2 h01 = __floats2half2_rn(vs.x - vt.x, vs.y - vt.y);
        __half2 h23 = __floats2half2_rn(vs.z - vt.z, vs.w - vt.w);
        uint2 u;
        u.x = *reinterpret_cast<const unsigned*>(&h01);
        u.y = *reinterpret_cast<const unsigned*>(&h23);
        pd[(size_t)ci * STR4] = u;

        vs.x = fabsf(vs.x); vs.y = fabsf(vs.y); vs.z = fabsf(vs.z); vs.w = fabsf(vs.w);
        vt.x = fabsf(vt.x); vt.y = fabsf(vt.y); vt.z = fabsf(vt.z); vt.w = fabsf(vt.w);
        as.x += vs.x; as.y += vs.y; as.z += vs.z; as.w += vs.w;
        at.x += vt.x; at.y += vt.y; at.z += vt.z; at.w += vt.w;

        stage[ci][tid] = make_float2((vs.x + vs.y) + (vs.z + vs.w),
                                     (vt.x + vt.y) + (vt.z + vt.w));
    }

    // spatial partials: exclusive slots, direct write
    float4* os = (float4*)(Gsp_s + (size_t)cc * (B * HWc) + b * HWc + hwbase) + tid;
    float4* ot = (float4*)(Gsp_t + (size_t)cc * (B * HWc) + b * HWc + hwbase) + tid;
    *os = as;
    *ot = at;

    __syncthreads();

    // warp w reduces channel c0+w
    float2 acc = make_float2(0.f, 0.f);
#pragma unroll
    for (int k = 0; k < TPB / 32; k++) {
        float2 v = stage[warp][lane + 32 * k];
        acc.x += v.x; acc.y += v.y;
    }
    F2D u2; u2.f2 = acc;
#pragma unroll
    for (int o = 16; o > 0; o >>= 1) {
        F2D v; v.d = __shfl_down_sync(0xffffffffu, u2.d, o);
        u2.f2.x += v.f2.x; u2.f2.y += v.f2.y;
    }
    if (lane == 0) {
        int idx = (b * Cc + c0 + warp) * NH + hh;
        Gcp_s[idx] = u2.f2.x;
        Gcp_t[idx] = u2.f2.y;
    }
}

__global__ void __launch_bounds__(TPB, 6)
pass1_kernel(const float* __restrict__ s1, const float* __restrict__ t1,
             const float* __restrict__ s2, const float* __restrict__ t2) {
    __shared__ float2 stage[CCH][TPB];   // 16 KB
    int bid = blockIdx.x;
    if (bid < TILES1)
        pass1_tile<C1, HW1, NC1, NH1>(s1, t1, g_d1,
            &g_Gs1p[0][0][0], &g_Gs1p[1][0][0],
            &g_Gc1p[0][0][0], &g_Gc1p[1][0][0], stage, bid);
    else
        pass1_tile<C2, HW2, NC2, NH2>(s2, t2, g_d2,
            &g_Gs2p[0][0][0], &g_Gs2p[1][0][0],
            &g_Gc2p[0][0][0], &g_Gc2p[1][0][0], stage, bid - TILES1);
}

// ---------------- softmax + lat (16 blocks) ----------------------------------
template <int Cc, int HWc, int NC, int NPART>
__device__ __forceinline__ void softmax_level(
    const float* __restrict__ Gsp_s, const float* __restrict__ Gsp_t,
    const float* __restrict__ Gcp_s, const float* __restrict__ Gcp_t,
    float* __restrict__ Ms, float* __restrict__ Mc,
    int b, float* zbuf, double* latout)
{
    const int tid = threadIdx.x;

    float latp = 0.f, mx = -INFINITY;
    for (int i = tid; i < HWc; i += STPB) {
        float ss = 0.f, st = 0.f;
#pragma unroll 8
        for (int p = 0; p < NC; p++) {
            ss += Gsp_s[(size_t)p * (B * HWc) + b * HWc + i];
            st += Gsp_t[(size_t)p * (B * HWc) + b * HWc + i];
        }
        float d = ss - st;
        latp += d * d;
        float z = (ss + st) * (2.0f / (float)Cc);   // /C then /T (T=0.5)
        zbuf[i] = z;
        mx = fmaxf(mx, z);
    }
    float m = blockReduceMax(mx);
    float se = 0.f;
    for (int i = tid; i < HWc; i += STPB) {
        float e = __expf(zbuf[i] - m);
        zbuf[i] = e;
        se += e;
    }
    float S = blockReduceSum(se);
    float sc = (float)HWc / S;
    for (int i = tid; i < HWc; i += STPB) Ms[b * HWc + i] = zbuf[i] * sc;
    float lat_s = blockReduceSum(latp);

    float latc = 0.f, mxc = -INFINITY;
    for (int i = tid; i < Cc; i += STPB) {
        float cs = 0.f, ct = 0.f;
#pragma unroll
        for (int k = 0; k < NPART; k++) {
            cs += Gcp_s[(size_t)(b * Cc + i) * NPART + k];
            ct += Gcp_t[(size_t)(b * Cc + i) * NPART + k];
        }
        float d = cs - ct;
        latc += d * d;
        float z = (cs + ct) * (2.0f / (float)HWc);
        zbuf[i] = z;
        mxc = fmaxf(mxc, z);
    }
    float m2 = blockReduceMax(mxc);
    float sec = 0.f;
    for (int i = tid; i < Cc; i += STPB) {
        float e = __expf(zbuf[i] - m2);
        zbuf[i] = e;
        sec += e;
    }
    float Sc = blockReduceSum(sec);
    float scc = (float)Cc / Sc;
    for (int i = tid; i < Cc; i += STPB) Mc[b * Cc + i] = zbuf[i] * scc;
    float lat_c = blockReduceSum(latc);

    if (tid == 0)
        *latout = (double)lat_s / ((double)Cc * (double)Cc) +
                  (double)lat_c / ((double)HWc * (double)HWc);
}

__global__ void softmax_kernel() {
    __shared__ float zbuf[HW1];   // 16 KB
    int bid = blockIdx.x;
    if (bid == 0 && threadIdx.x == 0) g_count = 0;   // reset last-block counter
    if (bid < B)
        softmax_level<C1, HW1, NC1, NH1>(
            &g_Gs1p[0][0][0], &g_Gs1p[1][0][0],
            &g_Gc1p[0][0][0], &g_Gc1p[1][0][0],
            g_Ms1, g_Mc1, bid, zbuf, &g_latpart[bid]);
    else
        softmax_level<C2, HW2, NC2, NH2>(
            &g_Gs2p[0][0][0], &g_Gs2p[1][0][0],
            &g_Gc2p[0][0][0], &g_Gc2p[1][0][0],
            g_Ms2, g_Mc2, bid - B, zbuf, &g_latpart[bid]);
}

// ---------------- pass 2: Ms in registers, fused final -----------------------
__device__ __forceinline__ void discard_l2(const void* p) {
    unsigned long long g;
    asm("cvta.to.global.u64 %0, %1;" : "=l"(g) : "l"(p));
    asm volatile("discard.global.L2 [%0], 128;" :: "l"(g) : "memory");
}

template <int Cc, int HWc>
__device__ __forceinline__ float pass2_block(
    const __half* __restrict__ dsrc,
    const float* __restrict__ Ms, const float* __restrict__ Mc,
    int b, int c0, int hwbase)
{
    const int tid = threadIdx.x;
    float4 ms = *(const float4*)(Ms + (size_t)b * HWc + hwbase + tid * 4);

    float acc = 0.f;
#pragma unroll
    for (int ci = 0; ci < P2CH; ci++) {
        const int c = c0 + ci;
        const uint2* p = (const uint2*)dsrc +
                         (((size_t)b * Cc + c) * HWc + hwbase) / 4 + tid;
        uint2 v = *p;
        float2 f0 = __half22float2(*reinterpret_cast<const __half2*>(&v.x));
        float2 f1 = __half22float2(*reinterpret_cast<const __half2*>(&v.y));
        float e = f0.x * f0.x * ms.x + f0.y * f0.y * ms.y
                + f1.x * f1.x * ms.z + f1.y * f1.y * ms.w;
        acc += e * Mc[b * Cc + c];
    }
    return acc;
}

template <int Cc, int HWc>
__device__ __forceinline__ void pass2_discard_block(
    const __half* dsrc, int b, int c0, int hwbase)
{
    const int ci = threadIdx.x >> 4;
    const int ln = threadIdx.x & 15;
    const __half* p = dsrc + ((size_t)b * Cc + c0 + ci) * HWc + hwbase + ln * 64;
    discard_l2(p);
}

__global__ void __launch_bounds__(TPB, 6)
pass2_kernel(float* out, int out_size) {
    int bid = blockIdx.x;
    float acc;
    int b, c0, hwbase;
    if (bid < P2B1) {
        b = bid / ((C1 / P2CH) * (HW1 / HWCH));
        int r = bid % ((C1 / P2CH) * (HW1 / HWCH));
        c0 = (r / (HW1 / HWCH)) * P2CH;
        hwbase = (r % (HW1 / HWCH)) * HWCH;
        acc = pass2_block<C1, HW1>(g_d1, g_Ms1, g_Mc1, b, c0, hwbase);
    } else {
        int id = bid - P2B1;
        b = id / (C2 / P2CH);
        c0 = (id % (C2 / P2CH)) * P2CH;
        hwbase = 0;
        acc = pass2_block<C2, HW2>(g_d2, g_Ms2, g_Mc2, b, c0, hwbase);
    }
    float bl = blockReduceSum(acc);

    if (bid < P2B1) pass2_discard_block<C1, HW1>(g_d1, b, c0, hwbase);
    else            pass2_discard_block<C2, HW2>(g_d2, b, c0, hwbase);

    __shared__ bool isLast;
    if (threadIdx.x == 0) {
        g_p2[bid] = bl;
        __threadfence();
        unsigned old = atomicAdd(&g_count, 1u);
        isLast = (old == P2TOT - 1);
    }
    __syncthreads();
    if (!isLast) return;

    __threadfence();
    int tid = threadIdx.x;
    double a1 = 0.0, a2 = 0.0;
    for (int i = tid; i < P2B1; i += TPB) a1 += (double)g_p2[i];
    for (int i = P2B1 + tid; i < P2TOT; i += TPB) a2 += (double)g_p2[i];

    __shared__ double sh1[32], sh2[32];
    int lane = tid & 31, warp = tid >> 5;
#pragma unroll
    for (int o = 16; o > 0; o >>= 1) {
        a1 += __shfl_down_sync(0xffffffffu, a1, o);
        a2 += __shfl_down_sync(0xffffffffu, a2, o);
    }
    if (lane == 0) { sh1[warp] = a1; sh2[warp] = a2; }
    __syncthreads();
    if (tid == 0) {
        double s1 = 0.0, s2 = 0.0;
        for (int w = 0; w < TPB / 32; w++) { s1 += sh1[w]; s2 += sh2[w]; }
        double lat = 0.0;
        for (int i = 0; i < 16; i++) lat += g_latpart[i];
        double lam = sqrt(s1) + sqrt(s2);
        double att = (4e-4 * lat + 2e-2 * lam) / (double)B / 2.0;   // ATT=1
        out[0] = (float)(att * (double)B);
        if (out_size > 1) out[1] = (float)att;
    }
}

// ---------------- launch ------------------------------------------------------
extern "C" void kernel_launch(void* const* d_in, const int* in_sizes, int n_in,
                              void* d_out, int out_size) {
    const float* stu1 = (const float*)d_in[1];
    const float* tea1 = (const float*)d_in[2];
    const float* stu2 = (const float*)d_in[3];
    const float* tea2 = (const float*)d_in[4];
    float* out = (float*)d_out;

    pass1_kernel<<<TILES1 + TILES2, TPB>>>(stu1, tea1, stu2, tea2);
    softmax_kernel<<<16, STPB>>>();
    pass2_kernel<<<P2TOT, TPB>>>(out, out_size);
}